// round 11
// baseline (speedup 1.0000x reference)
#include <cuda_runtime.h>
#include <math.h>

// Geometry: N_LAYERS=12, H=12, Vq(L)=2+13L, Vm=Vq+12, layer size 37*Vq+12
#define NP      32936     // P_TOTAL
#define NLM     32778     // _LM_BASE
#define NV      158       // V_TOTAL
#define NLAY    12
#define NWORDS  1030      // ceil(NP/32)
#define NCHUNK  258       // 128-element chunks per row (258*128 >= NP)
#define PW      1032      // pos words per row incl. zero pad (4*NCHUNK)
#define ROWSMAX 2048

__constant__ int c_lbase[NLAY] = {0, 86, 653, 1701, 3230, 5240, 7731,
                                  10703, 14156, 18090, 22505, 27401};

__device__ __align__(16) float g_pa[NP + 8];        // p*r + 0.5
__device__ __align__(16) float g_rw[NP + 8];        // 1/window
__device__ unsigned g_posbits[ROWSMAX][PW];         // per-row sign bitsets

// ---------------------------------------------------------------------------
__global__ void precompute_kernel(const float* __restrict__ sp) {
    int i = blockIdx.x * blockDim.x + threadIdx.x;
    if (i >= NP) return;
    double pd = 1.0 / (1.0 + exp(-(double)sp[i]));
    float p = (float)pd;
    float w = p * (1.0f - p);
    float pp = w * p + (1.0f - w) * p;      // value == p (matches ref)
    float r  = __fdiv_rn(1.0f, w);
    g_rw[i] = r;
    g_pa[i] = fmaf(pp, r, 0.5f);            // mask = sat(A - u*r)
}

// ---------------------------------------------------------------------------
__device__ __forceinline__ unsigned ext32(const unsigned* P, int s) {
    return __funnelshift_r(P[s >> 5], P[(s >> 5) + 1], s & 31);
}
__device__ __forceinline__ unsigned lenmask(int n) {        // n in (0,32]
    return (n >= 32) ? 0xffffffffu : ((1u << n) - 1u);
}
__device__ __forceinline__ int getbit(const unsigned* B, int p) {
    return (B[p >> 5] >> (p & 31)) & 1;
}
// spread low 8 bits to bit positions 0,4,...,28
__device__ __forceinline__ unsigned spread8(unsigned x) {
    x &= 0xFFu;
    x = (x | (x << 12)) & 0x000F000Fu;
    x = (x | (x << 6))  & 0x03030303u;
    x = (x | (x << 3))  & 0x11111111u;
    return x;
}

// ---------------------------------------------------------------------------
// Kernel A: pure streaming. One warp processes one 128-element chunk per step;
// 2 chunks per loop iteration for MLP. No smem, no block barriers.
__global__ __launch_bounds__(256) void stream_kernel(const float* __restrict__ unif,
                                                     float* __restrict__ out, int bz) {
    const int lane = threadIdx.x & 31;
    const int wid  = (blockIdx.x * blockDim.x + threadIdx.x) >> 5;
    const int nw   = (gridDim.x * blockDim.x) >> 5;
    const int total = bz * NCHUNK;
    const float4* pa4 = (const float4*)g_pa;
    const float4* rw4 = (const float4*)g_rw;

    for (int g0 = 2 * wid; g0 < total; g0 += 2 * nw) {
        #pragma unroll
        for (int s = 0; s < 2; s++) {
            int g = g0 + s;
            if (g >= total) break;
            unsigned row = (unsigned)g / NCHUNK;
            int c = g - (int)row * NCHUNK;
            int f = 32 * c + lane;
            const float4* u4 = (const float4*)(unif + (size_t)row * NP);
            float4*       o4 = (float4*)(out  + (size_t)row * NP);
            bool p0 = false, p1 = false, p2 = false, p3 = false;
            if (4 * f < NP) {
                float4 u = __ldcs(u4 + f);
                float4 a = __ldg(pa4 + f);
                float4 r = __ldg(rw4 + f);
                float m0 = __saturatef(fmaf(-u.x, r.x, a.x));
                float m1 = __saturatef(fmaf(-u.y, r.y, a.y));
                float m2 = __saturatef(fmaf(-u.z, r.z, a.z));
                float m3 = __saturatef(fmaf(-u.w, r.w, a.w));
                __stcs(o4 + f, make_float4(m0, m1, m2, m3));
                p0 = m0 > 0.0f; p1 = m1 > 0.0f; p2 = m2 > 0.0f; p3 = m3 > 0.0f;
            }
            unsigned b0 = __ballot_sync(0xffffffffu, p0);
            unsigned b1 = __ballot_sync(0xffffffffu, p1);
            unsigned b2 = __ballot_sync(0xffffffffu, p2);
            unsigned b3 = __ballot_sync(0xffffffffu, p3);
            if (lane < 4) {
                int sh = 8 * lane;
                unsigned w = spread8(b0 >> sh)
                           | (spread8(b1 >> sh) << 1)
                           | (spread8(b2 >> sh) << 2)
                           | (spread8(b3 >> sh) << 3);
                g_posbits[row][4 * c + lane] = w;   // lanes 0-3: one 16B sector
            }
        }
    }
}

// ---------------------------------------------------------------------------
// Per-row graph phases (one warp; verified R8 logic)
__device__ __forceinline__ void reach_fwd(const unsigned* pos, unsigned* sR, int lane) {
    for (int L = 0; L < NLAY; L++) {
        const int Vq = 2 + 13 * L, b = c_lbase[L];
        unsigned acc1 = 0;
        {
            int s = b + lane * Vq;
            #pragma unroll
            for (int k = 0; k < 5; k++)
                if (32 * k < Vq) acc1 |= ext32(pos, s + 32 * k) & sR[k];
        }
        bool a2 = false;
        if (lane < 4) {
            unsigned acc2 = 0;
            int s = b + (32 + lane) * Vq;
            #pragma unroll
            for (int k = 0; k < 5; k++)
                if (32 * k < Vq) acc2 |= ext32(pos, s + 32 * k) & sR[k];
            a2 = acc2 != 0;
        }
        unsigned b1 = __ballot_sync(0xffffffffu, acc1 != 0);
        unsigned b2 = __ballot_sync(0xffffffffu, a2);
        if (lane == 0) {
            #pragma unroll
            for (int h = 0; h < 12; h++) {
                unsigned q = (b1 >> h) & 1u;
                unsigned kk = (b1 >> (12 + h)) & 1u;
                unsigned v = (24 + h < 32) ? ((b1 >> (24 + h)) & 1u)
                                           : ((b2 >> (h - 8)) & 1u);
                if (q & kk & v) { int p = Vq + h; sR[p >> 5] |= 1u << (p & 31); }
            }
        }
        __syncwarp();
        const int Vm = Vq + 12, sm = b + 36 * Vq;
        bool am = false;
        if (lane < 5 && 32 * lane < Vm)
            am = (ext32(pos, sm + 32 * lane) & sR[lane]) != 0;
        unsigned bm = __ballot_sync(0xffffffffu, am);
        if (lane == 0 && bm) sR[Vm >> 5] |= 1u << (Vm & 31);
        __syncwarp();
    }
}

__device__ __forceinline__ void reach_bwd(const unsigned* pos, const unsigned* sR,
                                          unsigned* sO, int lane) {
    if (lane < 5) sO[lane] = ext32(pos, NLM + 32 * lane) & sR[lane] & lenmask(NV - 32 * lane);
    __syncwarp();
    for (int L = NLAY - 1; L >= 0; L--) {
        const int Vq = 2 + 13 * L, b = c_lbase[L], Vm = Vq + 12;
        int obm = getbit(sO, Vm) & getbit(sR, Vm);
        __syncwarp();
        if (obm && lane < 5 && 32 * lane < Vm)
            sO[lane] |= ext32(pos, b + 36 * Vq + 32 * lane) & sR[lane] & lenmask(Vm - 32 * lane);
        __syncwarp();
        unsigned wk[5] = {0, 0, 0, 0, 0};
        {
            int h = Vq + (lane % 12);
            if (getbit(sR, h) & getbit(sO, h)) {
                int s = b + lane * Vq;
                #pragma unroll
                for (int k = 0; k < 5; k++)
                    if (32 * k < Vq) wk[k] = ext32(pos, s + 32 * k) & sR[k] & lenmask(Vq - 32 * k);
            }
        }
        if (lane < 4) {
            int h = Vq + ((32 + lane) % 12);
            if (getbit(sR, h) & getbit(sO, h)) {
                int s = b + (32 + lane) * Vq;
                #pragma unroll
                for (int k = 0; k < 5; k++)
                    if (32 * k < Vq) wk[k] |= ext32(pos, s + 32 * k) & sR[k] & lenmask(Vq - 32 * k);
            }
        }
        #pragma unroll
        for (int k = 0; k < 5; k++) {
            unsigned red = __reduce_or_sync(0xffffffffu, wk[k]);
            if (lane == 0) sO[k] |= red;
        }
        __syncwarp();
    }
}

// ---------------------------------------------------------------------------
// Kernel B: one block per row — load bitset, graph phases, single prune pass.
__global__ __launch_bounds__(256) void prune_kernel(float* __restrict__ out) {
    __shared__ unsigned pos[PW];
    __shared__ unsigned sR[8];
    __shared__ unsigned sO[8];

    const int t = threadIdx.x, warp = t >> 5, lane = t & 31;
    const int row = blockIdx.x;
    float* orow = out + (size_t)row * NP;
    const unsigned* gp = g_posbits[row];

    for (int i = t; i < PW; i += 256) pos[i] = gp[i];
    if (t < 8) { sR[t] = (t == 0) ? 3u : 0u; sO[t] = 0u; }
    __syncthreads();

    if (warp == 0) {
        reach_fwd(pos, sR, lane);
        reach_bwd(pos, sR, sO, lane);
    }
    __syncthreads();

    // Single prune: kill = pos & ~(keepR & keepO)
    for (int g = t; g < 449; g += 256) {
        if (g < 444) {
            int L = g / 37, r = g % 37;
            int Vq = 2 + 13 * L, b = c_lbase[L];
            int s, len, hv;
            if (r < 36) { s = b + r * Vq; len = Vq; hv = Vq + (r % 12); }
            else        { s = b + 36 * Vq; len = Vq + 12; hv = Vq + 12; }
            int hk = getbit(sR, hv) & getbit(sO, hv);
            for (int k = 0; 32 * k < len; k++) {
                unsigned keep = hk ? (sR[k] & sO[k]) : 0u;
                unsigned kill = ext32(pos, s + 32 * k) & ~keep & lenmask(len - 32 * k);
                while (kill) {
                    int bp = __ffs(kill) - 1; kill &= kill - 1;
                    orow[s + 32 * k + bp] = 0.0f;
                }
            }
        } else {
            int k = g - 444;
            int s = NLM + 32 * k;
            unsigned kill = ext32(pos, s) & ~(sR[k] & sO[k]) & lenmask(NV - 32 * k);
            while (kill) {
                int bp = __ffs(kill) - 1; kill &= kill - 1;
                orow[s + bp] = 0.0f;
            }
        }
    }
}

// ---------------------------------------------------------------------------
extern "C" void kernel_launch(void* const* d_in, const int* in_sizes, int n_in,
                              void* d_out, int out_size) {
    const float* sp   = (const float*)d_in[0];
    const float* unif = (const float*)d_in[1];
    float*       out  = (float*)d_out;
    int bz = in_sizes[1] / NP;
    if (bz > ROWSMAX) bz = ROWSMAX;

    precompute_kernel<<<(NP + 255) / 256, 256>>>(sp);
    stream_kernel<<<1184, 256>>>(unif, out, bz);
    prune_kernel<<<bz, 256>>>(out);
}

// round 13
// speedup vs baseline: 1.2514x; 1.2514x over previous
#include <cuda_runtime.h>
#include <math.h>

// Geometry: N_LAYERS=12, H=12, Vq(L)=2+13L, Vm=Vq+12, layer size 37*Vq+12
#define NP      32936     // P_TOTAL
#define NLM     32778     // _LM_BASE
#define NV      158       // V_TOTAL
#define NLAY    12
#define NWORDS  1030      // ceil(NP/32)
#define NTHR    256
#define NCHUNK  258       // 128-element chunks (NCHUNK even)

__constant__ int c_lbase[NLAY] = {0, 86, 653, 1701, 3230, 5240, 7731,
                                  10703, 14156, 18090, 22505, 27401};

__device__ __align__(16) float g_pa[NP + 8];   // p*r + 0.5
__device__ __align__(16) float g_rw[NP + 8];   // 1/window

// ---------------------------------------------------------------------------
__global__ void precompute_kernel(const float* __restrict__ sp) {
    int i = blockIdx.x * blockDim.x + threadIdx.x;
    if (i >= NP) return;
    double pd = 1.0 / (1.0 + exp(-(double)sp[i]));
    float p = (float)pd;
    float w = p * (1.0f - p);
    float pp = w * p + (1.0f - w) * p;      // value == p (matches ref)
    float r  = __fdiv_rn(1.0f, w);
    g_rw[i] = r;
    g_pa[i] = fmaf(pp, r, 0.5f);            // mask = sat(A - u*r)
}

// ---------------------------------------------------------------------------
__device__ __forceinline__ unsigned ext32(const unsigned* P, int s) {
    return __funnelshift_r(P[s >> 5], P[(s >> 5) + 1], s & 31);
}
__device__ __forceinline__ unsigned lenmask(int n) {        // n in (0,32]
    return (n >= 32) ? 0xffffffffu : ((1u << n) - 1u);
}
__device__ __forceinline__ int getbit(const unsigned* B, int p) {
    return (B[p >> 5] >> (p & 31)) & 1;
}
// spread low 8 bits to bit positions 0,4,...,28
__device__ __forceinline__ unsigned spread8(unsigned x) {
    x &= 0xFFu;
    x = (x | (x << 12)) & 0x000F000Fu;
    x = (x | (x << 6))  & 0x03030303u;
    x = (x | (x << 3))  & 0x11111111u;
    return x;
}

// ---------------------------------------------------------------------------
__global__ __launch_bounds__(NTHR, 8) void mask_kernel(const float* __restrict__ unif,
                                                       float* __restrict__ out) {
    __shared__ unsigned pos[NWORDS + 2];
    __shared__ unsigned sR[8];
    __shared__ unsigned sO[8];

    const int t = threadIdx.x, warp = t >> 5, lane = t & 31;
    const size_t rowoff = (size_t)blockIdx.x * NP;
    const float4* u4  = (const float4*)(unif + rowoff);
    float4*       o4  = (float4*)(out + rowoff);
    const float4* pa4 = (const float4*)g_pa;
    const float4* rw4 = (const float4*)g_rw;
    float*        orow = out + rowoff;

    if (t < 8) { sR[t] = (t == 0) ? 3u : 0u; sO[t] = 0u; }
    if (t == 0) { pos[NWORDS] = 0u; pos[NWORDS + 1] = 0u; }

    // ---- Pass 1: paired-chunk unroll; 6 LDG.128 in flight before ballots ----
    for (int c0 = 2 * warp; c0 < NCHUNK; c0 += 2 * (NTHR / 32)) {
        int fA = 32 * c0 + lane;              // chunk A float4 index
        int fB = fA + 32;                     // chunk B (c0+1 < NCHUNK since even)
        bool inA = 4 * fA < NP, inB = 4 * fB < NP;

        float4 uA, aA, rA, uB, aB, rB;
        if (inA) { uA = __ldcs(u4 + fA); aA = __ldg(pa4 + fA); rA = __ldg(rw4 + fA); }
        if (inB) { uB = __ldcs(u4 + fB); aB = __ldg(pa4 + fB); rB = __ldg(rw4 + fB); }

        bool qa0 = false, qa1 = false, qa2 = false, qa3 = false;
        bool qb0 = false, qb1 = false, qb2 = false, qb3 = false;
        if (inA) {
            float m0 = __saturatef(fmaf(-uA.x, rA.x, aA.x));
            float m1 = __saturatef(fmaf(-uA.y, rA.y, aA.y));
            float m2 = __saturatef(fmaf(-uA.z, rA.z, aA.z));
            float m3 = __saturatef(fmaf(-uA.w, rA.w, aA.w));
            __stcs(o4 + fA, make_float4(m0, m1, m2, m3));
            qa0 = m0 > 0.0f; qa1 = m1 > 0.0f; qa2 = m2 > 0.0f; qa3 = m3 > 0.0f;
        }
        if (inB) {
            float n0 = __saturatef(fmaf(-uB.x, rB.x, aB.x));
            float n1 = __saturatef(fmaf(-uB.y, rB.y, aB.y));
            float n2 = __saturatef(fmaf(-uB.z, rB.z, aB.z));
            float n3 = __saturatef(fmaf(-uB.w, rB.w, aB.w));
            __stcs(o4 + fB, make_float4(n0, n1, n2, n3));
            qb0 = n0 > 0.0f; qb1 = n1 > 0.0f; qb2 = n2 > 0.0f; qb3 = n3 > 0.0f;
        }
        unsigned a0 = __ballot_sync(0xffffffffu, qa0);
        unsigned a1 = __ballot_sync(0xffffffffu, qa1);
        unsigned a2 = __ballot_sync(0xffffffffu, qa2);
        unsigned a3 = __ballot_sync(0xffffffffu, qa3);
        unsigned b0 = __ballot_sync(0xffffffffu, qb0);
        unsigned b1 = __ballot_sync(0xffffffffu, qb1);
        unsigned b2 = __ballot_sync(0xffffffffu, qb2);
        unsigned b3 = __ballot_sync(0xffffffffu, qb3);
        if (lane < 8) {
            int sub = lane & 3, cs = lane >> 2;      // cs=0 -> chunk A, 1 -> B
            unsigned x0 = cs ? b0 : a0, x1 = cs ? b1 : a1;
            unsigned x2 = cs ? b2 : a2, x3 = cs ? b3 : a3;
            int sh = 8 * sub;
            unsigned w = spread8(x0 >> sh)
                       | (spread8(x1 >> sh) << 1)
                       | (spread8(x2 >> sh) << 2)
                       | (spread8(x3 >> sh) << 3);
            int wi = 4 * (c0 + cs) + sub;
            if (wi < NWORDS) pos[wi] = w;
        }
    }
    __syncthreads();

    // ---- Forward reachability R (warp 0, bit-parallel) ----
    if (warp == 0) {
        for (int L = 0; L < NLAY; L++) {
            const int Vq = 2 + 13 * L, b = c_lbase[L];
            unsigned acc1 = 0;
            {
                int s = b + lane * Vq;
                #pragma unroll
                for (int k = 0; k < 5; k++)
                    if (32 * k < Vq) acc1 |= ext32(pos, s + 32 * k) & sR[k];
            }
            bool a2 = false;
            if (lane < 4) {
                unsigned acc2 = 0;
                int s = b + (32 + lane) * Vq;
                #pragma unroll
                for (int k = 0; k < 5; k++)
                    if (32 * k < Vq) acc2 |= ext32(pos, s + 32 * k) & sR[k];
                a2 = acc2 != 0;
            }
            unsigned b1 = __ballot_sync(0xffffffffu, acc1 != 0);
            unsigned b2 = __ballot_sync(0xffffffffu, a2);
            if (lane == 0) {
                #pragma unroll
                for (int h = 0; h < 12; h++) {
                    unsigned q = (b1 >> h) & 1u;
                    unsigned kk = (b1 >> (12 + h)) & 1u;
                    unsigned v = (24 + h < 32) ? ((b1 >> (24 + h)) & 1u)
                                               : ((b2 >> (h - 8)) & 1u);
                    if (q & kk & v) { int p = Vq + h; sR[p >> 5] |= 1u << (p & 31); }
                }
            }
            __syncwarp();
            const int Vm = Vq + 12, sm = b + 36 * Vq;
            bool am = false;
            if (lane < 5 && 32 * lane < Vm)
                am = (ext32(pos, sm + 32 * lane) & sR[lane]) != 0;
            unsigned bm = __ballot_sync(0xffffffffu, am);
            if (lane == 0 && bm) sR[Vm >> 5] |= 1u << (Vm & 31);
            __syncwarp();
        }
        // ---- Backward reachability O on R-pruned graph (keep(R) folded) ----
        if (lane < 5) sO[lane] = ext32(pos, NLM + 32 * lane) & sR[lane] & lenmask(NV - 32 * lane);
        __syncwarp();
        for (int L = NLAY - 1; L >= 0; L--) {
            const int Vq = 2 + 13 * L, b = c_lbase[L], Vm = Vq + 12;
            int obm = getbit(sO, Vm) & getbit(sR, Vm);
            __syncwarp();
            if (obm && lane < 5 && 32 * lane < Vm)
                sO[lane] |= ext32(pos, b + 36 * Vq + 32 * lane) & sR[lane] & lenmask(Vm - 32 * lane);
            __syncwarp();
            unsigned wk[5] = {0, 0, 0, 0, 0};
            {
                int h = Vq + (lane % 12);
                if (getbit(sR, h) & getbit(sO, h)) {
                    int s = b + lane * Vq;
                    #pragma unroll
                    for (int k = 0; k < 5; k++)
                        if (32 * k < Vq) wk[k] = ext32(pos, s + 32 * k) & sR[k] & lenmask(Vq - 32 * k);
                }
            }
            if (lane < 4) {
                int h = Vq + ((32 + lane) % 12);
                if (getbit(sR, h) & getbit(sO, h)) {
                    int s = b + (32 + lane) * Vq;
                    #pragma unroll
                    for (int k = 0; k < 5; k++)
                        if (32 * k < Vq) wk[k] |= ext32(pos, s + 32 * k) & sR[k] & lenmask(Vq - 32 * k);
                }
            }
            #pragma unroll
            for (int k = 0; k < 5; k++) {
                unsigned red = __reduce_or_sync(0xffffffffu, wk[k]);
                if (lane == 0) sO[k] |= red;
            }
            __syncwarp();
        }
    }
    __syncthreads();

    // ---- Single final prune: kill = pos & ~(keepR & keepO) ----
    for (int g = t; g < 449; g += NTHR) {
        if (g < 444) {
            int L = g / 37, r = g % 37;
            int Vq = 2 + 13 * L, b = c_lbase[L];
            int s, len, hv;
            if (r < 36) { s = b + r * Vq; len = Vq; hv = Vq + (r % 12); }
            else        { s = b + 36 * Vq; len = Vq + 12; hv = Vq + 12; }
            int hk = getbit(sR, hv) & getbit(sO, hv);
            for (int k = 0; 32 * k < len; k++) {
                unsigned keep = hk ? (sR[k] & sO[k]) : 0u;
                unsigned kill = ext32(pos, s + 32 * k) & ~keep & lenmask(len - 32 * k);
                while (kill) {
                    int bp = __ffs(kill) - 1; kill &= kill - 1;
                    orow[s + 32 * k + bp] = 0.0f;
                }
            }
        } else {
            int k = g - 444;
            int s = NLM + 32 * k;
            unsigned kill = ext32(pos, s) & ~(sR[k] & sO[k]) & lenmask(NV - 32 * k);
            while (kill) {
                int bp = __ffs(kill) - 1; kill &= kill - 1;
                orow[s + bp] = 0.0f;
            }
        }
    }
}

// ---------------------------------------------------------------------------
extern "C" void kernel_launch(void* const* d_in, const int* in_sizes, int n_in,
                              void* d_out, int out_size) {
    const float* sp   = (const float*)d_in[0];
    const float* unif = (const float*)d_in[1];
    float*       out  = (float*)d_out;
    int bz = in_sizes[1] / NP;

    precompute_kernel<<<(NP + 255) / 256, 256>>>(sp);
    mask_kernel<<<bz, NTHR>>>(unif, out);
}